// round 9
// baseline (speedup 1.0000x reference)
#include <cuda_runtime.h>
#include <cstddef>

constexpr int BATCH = 32;
constexpr int L     = 2048;
constexpr int R     = 1024;   // RNN_SIZE
constexpr int A     = 512;    // ATT_HID
constexpr int CH    = 16;     // L-chunks for weighted sum
constexpr int LC    = L / CH; // 128 l's per chunk
constexpr unsigned FULL = 0xffffffffu;

// Scratch (no allocation allowed; __device__ globals zero-initialized)
__device__ float g_att_h[BATCH * A];
__device__ float g_escore[BATCH * L];     // exp(score); masked slots = 0.0f
__device__ int   g_lidx[BATCH * L];       // per-b compacted unmasked l indices
__device__ int   g_lcnt[BATCH];
__device__ __align__(16) float g_part[(size_t)CH * BATCH * R]; // 2 MB partials
__device__ int   g_cnt[BATCH];            // completion counters (self-resetting)
__device__ int   g_mask_u8;

__device__ __forceinline__ float4 ldcs4(const float4* p) { return __ldcs(p); }
__device__ __forceinline__ float4 ldcg4(const float4* p) { return __ldcg(p); }

// ---------------------------------------------------------------------------
// k_att_h: one warp per (a, b-octet). 256 work blocks + 1 mask-dtype probe.
// Probe scans first 64KB of mask (safe for uint8 [64KB] or int32 [256KB]):
// int32 bool masks only set byte 0 of each word; uint8 sets upper bytes w.h.p.
// ---------------------------------------------------------------------------
__global__ void k_att_h(const float* __restrict__ h,
                        const float* __restrict__ Wh,
                        const float* __restrict__ bh,
                        const unsigned int* __restrict__ mw) {
    if (blockIdx.x == 256) {   // mask dtype probe
        __shared__ unsigned int red[256];
        unsigned int v = 0;
        for (int w = threadIdx.x; w < 16384; w += 256) v |= mw[w];
        red[threadIdx.x] = v;
        __syncthreads();
        for (int o = 128; o > 0; o >>= 1) {
            if (threadIdx.x < o) red[threadIdx.x] |= red[threadIdx.x + o];
            __syncthreads();
        }
        if (threadIdx.x == 0) g_mask_u8 = (red[0] & 0xFFFFFF00u) ? 1 : 0;
        return;
    }
    int wrp  = threadIdx.x >> 5;
    int lane = threadIdx.x & 31;
    int gw   = blockIdx.x * 8 + wrp;      // 0..2047
    int a    = gw & 511;
    int bg   = gw >> 9;                    // b-octet 0..3
    const float4* w4 = (const float4*)(Wh + (size_t)a * R);
    float4 wv[8];
#pragma unroll
    for (int j = 0; j < 8; j++) wv[j] = w4[lane + j * 32];
    float bias = bh[a];

#pragma unroll
    for (int bb = 0; bb < 8; bb++) {
        int b = bg * 8 + bb;
        const float4* h4 = (const float4*)(h + (size_t)b * R);
        float acc = 0.f;
#pragma unroll
        for (int j = 0; j < 8; j++) {
            float4 hv = __ldg(h4 + lane + j * 32);
            acc += hv.x * wv[j].x + hv.y * wv[j].y + hv.z * wv[j].z + hv.w * wv[j].w;
        }
#pragma unroll
        for (int o = 16; o > 0; o >>= 1) acc += __shfl_down_sync(FULL, acc, o);
        if (lane == 0) g_att_h[b * A + a] = acc + bias;
    }
}

// ---------------------------------------------------------------------------
// k_compact: per b, ordered list of unmasked l's + 0.0f pre-fill of masked
// escore slots (exp(-1e8) == 0 exactly, matching the reference's underflow).
// 8 warps each compact a 256-l segment (two-pass ballot + smem prefix).
// ---------------------------------------------------------------------------
__global__ void k_compact(const unsigned char* __restrict__ m8,
                          const int* __restrict__ m32) {
    int b = blockIdx.x, t = threadIdx.x;
    int w = t >> 5, lane = t & 31;
    int u8 = g_mask_u8;
    __shared__ int wcnt[8];
    __shared__ int woff[9];

    unsigned keepbits[8];
    int cnt = 0;
    unsigned mykeep = 0;
#pragma unroll
    for (int r = 0; r < 8; r++) {
        int l = w * 256 + r * 32 + lane;
        int idx = b * L + l;
        bool keep = u8 ? (m8[idx] == 0) : (m32[idx] == 0);
        if (!keep) g_escore[idx] = 0.0f;          // masked weight is exactly 0
        unsigned m = __ballot_sync(FULL, keep);
        keepbits[r] = m;
        if (keep) mykeep |= (1u << r);
        cnt += __popc(m);
    }
    if (lane == 0) wcnt[w] = cnt;
    __syncthreads();
    if (t == 0) {
        woff[0] = 0;
#pragma unroll
        for (int i = 0; i < 8; i++) woff[i + 1] = woff[i] + wcnt[i];
        g_lcnt[b] = woff[8];
    }
    __syncthreads();

    int base = woff[w];
#pragma unroll
    for (int r = 0; r < 8; r++) {
        unsigned m = keepbits[r];
        if (mykeep & (1u << r)) {
            int pos = base + __popc(m & ((1u << lane) - 1u));
            g_lidx[b * L + pos] = w * 256 + r * 32 + lane;
        }
        base += __popc(m);
    }
}

// Accurate fast tanh: 2 MUFU (EX2 + RCP) + FMAs, rel err ~1e-7.
__device__ __forceinline__ float tanh_fast(float x) {
    float ax = fabsf(x);
    float e  = __expf(-2.0f * ax);
    float t  = __fdividef(1.0f - e, 1.0f + e);
    return copysignf(t, x);
}

// ---------------------------------------------------------------------------
// scores over the COMPACT list only; stores exp(score). |score| <= ~23
// (|b_a| + sum|W_a|), so exp(score) can neither overflow nor underflow, and
// exp(s)/sum(exp(s)) is ulp-equivalent to the reference's max-shifted softmax.
// ---------------------------------------------------------------------------
__global__ void k_scores(const float* __restrict__ p,
                         const float* __restrict__ Wa,
                         const float* __restrict__ ba) {
    int b  = blockIdx.x >> 8;
    int jg = blockIdx.x & 255;
    int cnt = g_lcnt[b];
    if (jg * 8 >= cnt) return;

    __shared__ __align__(16) float sa[A];
    __shared__ __align__(16) float sw[A];
    int t = threadIdx.x;
    sa[t]       = g_att_h[b * A + t];
    sa[t + 256] = g_att_h[b * A + t + 256];
    sw[t]       = Wa[t];
    sw[t + 256] = Wa[t + 256];
    __syncthreads();

    int w = t >> 5, lane = t & 31;
    int j = jg * 8 + w;
    if (j >= cnt) return;
    int l = 0;
    if (lane == 0) l = g_lidx[b * L + j];
    l = __shfl_sync(FULL, l, 0);
    int idx = b * L + l;

    const float4* p4 = (const float4*)(p + (size_t)idx * A);
    const float4* a4 = (const float4*)sa;
    const float4* w4 = (const float4*)sw;

    float4 pv[4];
#pragma unroll
    for (int j2 = 0; j2 < 4; j2++) pv[j2] = ldcs4(p4 + lane + j2 * 32);

    float acc = 0.f;
#pragma unroll
    for (int j2 = 0; j2 < 4; j2++) {
        int i = lane + j2 * 32;
        float4 av = a4[i], wv = w4[i];
        acc += tanh_fast(pv[j2].x + av.x) * wv.x;
        acc += tanh_fast(pv[j2].y + av.y) * wv.y;
        acc += tanh_fast(pv[j2].z + av.z) * wv.z;
        acc += tanh_fast(pv[j2].w + av.w) * wv.w;
    }
#pragma unroll
    for (int o = 16; o > 0; o >>= 1) acc += __shfl_down_sync(FULL, acc, o);
    if (lane == 0) g_escore[idx] = __expf(acc + ba[0]);
}

// ---------------------------------------------------------------------------
// k_wsum: per-(chunk, b) weighted-sum partials. Prologue computes the FULL
// softmax denominator from the 8KB L2-resident escore row with a fixed-order
// smem tree (deterministic), eliminating the separate smax kernel. Weight =
// escore * (1/sum); zero escores (masked) are ballot-compacted away, which is
// bit-exact (reference contributes exactly 0 for those rows). Fused final
// reduce via per-b counter with fence -> barrier -> atomic release ordering.
// ---------------------------------------------------------------------------
__global__ void k_wsum(const float* __restrict__ af, float* __restrict__ out) {
    int c = blockIdx.x, b = blockIdx.y, t = threadIdx.x;
    __shared__ float swraw[LC];
    __shared__ float red[256];
    __shared__ float swv[LC];
    __shared__ int   sidx[LC];
    __shared__ int   scount;
    __shared__ float s_inv;
    __shared__ int   s_ticket;

    // Full-row softmax denominator (deterministic fixed-order reduction).
    float part = 0.f;
#pragma unroll
    for (int k = 0; k < 8; k++) part += g_escore[b * L + t + k * 256];
    red[t] = part;
    int lbase = b * L + c * LC;
    if (t < LC) swraw[t] = g_escore[lbase + t];
    __syncthreads();
    for (int o = 128; o > 0; o >>= 1) {
        if (t < o) red[t] += red[t + o];
        __syncthreads();
    }
    if (t == 0) s_inv = 1.0f / red[0];
    __syncthreads();

    // Ballot-compact nonzero weights (weight = escore * inv).
    if (t < 32) {
        int base = 0;
        float inv = s_inv;
#pragma unroll
        for (int k = 0; k < LC; k += 32) {
            float e = swraw[k + t];
            unsigned m = __ballot_sync(FULL, e != 0.f);
            if (e != 0.f) {
                int pos = base + __popc(m & ((1u << t) - 1u));
                swv[pos]  = e * inv;
                sidx[pos] = k + t;
            }
            base += __popc(m);
        }
        if (t == 0) scount = base;
    }
    __syncthreads();

    const float4* a4 = (const float4*)(af + (size_t)lbase * R);
    float4 acc = make_float4(0.f, 0.f, 0.f, 0.f);
    int n = scount;
    int j = 0;
    for (; j + 4 <= n; j += 4) {
        float w0 = swv[j],     w1 = swv[j + 1];
        float w2 = swv[j + 2], w3 = swv[j + 3];
        float4 v0 = ldcs4(a4 + (size_t)sidx[j]     * (R / 4) + t);
        float4 v1 = ldcs4(a4 + (size_t)sidx[j + 1] * (R / 4) + t);
        float4 v2 = ldcs4(a4 + (size_t)sidx[j + 2] * (R / 4) + t);
        float4 v3 = ldcs4(a4 + (size_t)sidx[j + 3] * (R / 4) + t);
        acc.x += w0 * v0.x; acc.y += w0 * v0.y; acc.z += w0 * v0.z; acc.w += w0 * v0.w;
        acc.x += w1 * v1.x; acc.y += w1 * v1.y; acc.z += w1 * v1.z; acc.w += w1 * v1.w;
        acc.x += w2 * v2.x; acc.y += w2 * v2.y; acc.z += w2 * v2.z; acc.w += w2 * v2.w;
        acc.x += w3 * v3.x; acc.y += w3 * v3.y; acc.z += w3 * v3.z; acc.w += w3 * v3.w;
    }
    for (; j < n; j++) {
        float w  = swv[j];
        float4 v = ldcs4(a4 + (size_t)sidx[j] * (R / 4) + t);
        acc.x += w * v.x; acc.y += w * v.y; acc.z += w * v.z; acc.w += w * v.w;
    }
    ((float4*)(g_part + ((size_t)c * BATCH + b) * R))[t] = acc;

    // Fused final reduce with correct release ordering.
    __threadfence();     // each thread: my partial store ordered
    __syncthreads();     // all threads fenced => whole block's partial visible
    if (t == 0) s_ticket = atomicAdd(&g_cnt[b], 1);
    __syncthreads();
    if (s_ticket == CH - 1) {
        float4 s = make_float4(0.f, 0.f, 0.f, 0.f);
#pragma unroll
        for (int cc = 0; cc < CH; cc++) {
            float4 v = ldcg4((const float4*)(g_part + ((size_t)cc * BATCH + b) * R) + t);
            s.x += v.x; s.y += v.y; s.z += v.z; s.w += v.w;
        }
        ((float4*)(out + (size_t)b * R))[t] = s;
        if (t == 0) g_cnt[b] = 0;   // self-reset for next launch/replay
    }
}

// ---------------------------------------------------------------------------
extern "C" void kernel_launch(void* const* d_in, const int* in_sizes, int n_in,
                              void* d_out, int out_size) {
    const float* h    = (const float*)d_in[0];
    const float* af   = (const float*)d_in[1];
    const float* p    = (const float*)d_in[2];
    const void*  mask = d_in[3];
    const float* Wh   = (const float*)d_in[4];
    const float* bh   = (const float*)d_in[5];
    const float* Wa   = (const float*)d_in[6];
    const float* ba   = (const float*)d_in[7];
    float* out = (float*)d_out;

    k_att_h<<<257, 256>>>(h, Wh, bh, (const unsigned int*)mask);
    k_compact<<<BATCH, 256>>>((const unsigned char*)mask, (const int*)mask);
    k_scores<<<8192, 256>>>(p, Wa, ba);
    k_wsum<<<dim3(CH, BATCH), 256>>>(af, out);
}

// round 10
// speedup vs baseline: 1.1715x; 1.1715x over previous
#include <cuda_runtime.h>
#include <cstddef>

constexpr int BATCH = 32;
constexpr int L     = 2048;
constexpr int R     = 1024;   // RNN_SIZE
constexpr int A     = 512;    // ATT_HID
constexpr int CH    = 16;     // L-chunks for weighted sum
constexpr int LC    = L / CH; // 128 l's per chunk
constexpr int SC    = 8;      // sum chunks per batch
constexpr int SLEN  = L / SC; // 256 escores per sum block
constexpr unsigned FULL = 0xffffffffu;

// Scratch (no allocation allowed; __device__ globals zero-initialized)
__device__ float g_att_h[BATCH * A];
__device__ float g_escore[BATCH * L];     // exp(score); masked slots = 0.0f
__device__ int   g_lidx[BATCH * L];       // per-b compacted unmasked l indices
__device__ int   g_lcnt[BATCH];
__device__ float g_ps[BATCH * SC];        // partial sums of escore
__device__ __align__(16) float g_part[(size_t)CH * BATCH * R]; // 2 MB partials
__device__ int   g_cnt[BATCH];            // completion counters (self-resetting)
__device__ int   g_mask_u8;

__device__ __forceinline__ float4 ldcs4(const float4* p) { return __ldcs(p); }
__device__ __forceinline__ float4 ldcg4(const float4* p) { return __ldcg(p); }

// ---------------------------------------------------------------------------
// k_att_h: one warp per (a, b-octet). 256 work blocks + 1 mask-dtype probe.
// Probe scans first 64KB of mask (safe for uint8 [64KB] or int32 [256KB]):
// int32 bool masks only set byte 0 of each word; uint8 sets upper bytes w.h.p.
// ---------------------------------------------------------------------------
__global__ void k_att_h(const float* __restrict__ h,
                        const float* __restrict__ Wh,
                        const float* __restrict__ bh,
                        const unsigned int* __restrict__ mw) {
    if (blockIdx.x == 256) {   // mask dtype probe
        __shared__ unsigned int red[256];
        unsigned int v = 0;
        for (int w = threadIdx.x; w < 16384; w += 256) v |= mw[w];
        red[threadIdx.x] = v;
        __syncthreads();
        for (int o = 128; o > 0; o >>= 1) {
            if (threadIdx.x < o) red[threadIdx.x] |= red[threadIdx.x + o];
            __syncthreads();
        }
        if (threadIdx.x == 0) g_mask_u8 = (red[0] & 0xFFFFFF00u) ? 1 : 0;
        return;
    }
    int wrp  = threadIdx.x >> 5;
    int lane = threadIdx.x & 31;
    int gw   = blockIdx.x * 8 + wrp;      // 0..2047
    int a    = gw & 511;
    int bg   = gw >> 9;                    // b-octet 0..3
    const float4* w4 = (const float4*)(Wh + (size_t)a * R);
    float4 wv[8];
#pragma unroll
    for (int j = 0; j < 8; j++) wv[j] = w4[lane + j * 32];
    float bias = bh[a];

#pragma unroll
    for (int bb = 0; bb < 8; bb++) {
        int b = bg * 8 + bb;
        const float4* h4 = (const float4*)(h + (size_t)b * R);
        float acc = 0.f;
#pragma unroll
        for (int j = 0; j < 8; j++) {
            float4 hv = __ldg(h4 + lane + j * 32);
            acc += hv.x * wv[j].x + hv.y * wv[j].y + hv.z * wv[j].z + hv.w * wv[j].w;
        }
#pragma unroll
        for (int o = 16; o > 0; o >>= 1) acc += __shfl_down_sync(FULL, acc, o);
        if (lane == 0) g_att_h[b * A + a] = acc + bias;
    }
}

// ---------------------------------------------------------------------------
// k_compact: per b, ordered list of unmasked l's + 0.0f pre-fill of masked
// escore slots (exp(-1e8) == 0 exactly, matching the reference's underflow).
// 8 warps each compact a 256-l segment (two-pass ballot + smem prefix).
// ---------------------------------------------------------------------------
__global__ void k_compact(const unsigned char* __restrict__ m8,
                          const int* __restrict__ m32) {
    int b = blockIdx.x, t = threadIdx.x;
    int w = t >> 5, lane = t & 31;
    int u8 = g_mask_u8;
    __shared__ int wcnt[8];
    __shared__ int woff[9];

    unsigned keepbits[8];
    int cnt = 0;
    unsigned mykeep = 0;
#pragma unroll
    for (int r = 0; r < 8; r++) {
        int l = w * 256 + r * 32 + lane;
        int idx = b * L + l;
        bool keep = u8 ? (m8[idx] == 0) : (m32[idx] == 0);
        if (!keep) g_escore[idx] = 0.0f;          // masked weight is exactly 0
        unsigned m = __ballot_sync(FULL, keep);
        keepbits[r] = m;
        if (keep) mykeep |= (1u << r);
        cnt += __popc(m);
    }
    if (lane == 0) wcnt[w] = cnt;
    __syncthreads();
    if (t == 0) {
        woff[0] = 0;
#pragma unroll
        for (int i = 0; i < 8; i++) woff[i + 1] = woff[i] + wcnt[i];
        g_lcnt[b] = woff[8];
    }
    __syncthreads();

    int base = woff[w];
#pragma unroll
    for (int r = 0; r < 8; r++) {
        unsigned m = keepbits[r];
        if (mykeep & (1u << r)) {
            int pos = base + __popc(m & ((1u << lane) - 1u));
            g_lidx[b * L + pos] = w * 256 + r * 32 + lane;
        }
        base += __popc(m);
    }
}

// Accurate fast tanh: 2 MUFU (EX2 + RCP) + FMAs, rel err ~1e-7.
__device__ __forceinline__ float tanh_fast(float x) {
    float ax = fabsf(x);
    float e  = __expf(-2.0f * ax);
    float t  = __fdividef(1.0f - e, 1.0f + e);
    return copysignf(t, x);
}

// ---------------------------------------------------------------------------
// scores over the COMPACT list only; stores exp(score). |score| <= ~23
// (|b_a| + sum|W_a|·1), so exp can neither overflow nor underflow, and
// exp(s)/sum(exp(s)) is ulp-equivalent to the reference's shifted softmax.
// ---------------------------------------------------------------------------
__global__ void k_scores(const float* __restrict__ p,
                         const float* __restrict__ Wa,
                         const float* __restrict__ ba) {
    int b  = blockIdx.x >> 8;
    int jg = blockIdx.x & 255;
    int cnt = g_lcnt[b];
    if (jg * 8 >= cnt) return;

    __shared__ __align__(16) float sa[A];
    __shared__ __align__(16) float sw[A];
    int t = threadIdx.x;
    sa[t]       = g_att_h[b * A + t];
    sa[t + 256] = g_att_h[b * A + t + 256];
    sw[t]       = Wa[t];
    sw[t + 256] = Wa[t + 256];
    __syncthreads();

    int w = t >> 5, lane = t & 31;
    int j = jg * 8 + w;
    if (j >= cnt) return;
    int l = 0;
    if (lane == 0) l = g_lidx[b * L + j];
    l = __shfl_sync(FULL, l, 0);
    int idx = b * L + l;

    const float4* p4 = (const float4*)(p + (size_t)idx * A);
    const float4* a4 = (const float4*)sa;
    const float4* w4 = (const float4*)sw;

    float4 pv[4];
#pragma unroll
    for (int j2 = 0; j2 < 4; j2++) pv[j2] = ldcs4(p4 + lane + j2 * 32);

    float acc = 0.f;
#pragma unroll
    for (int j2 = 0; j2 < 4; j2++) {
        int i = lane + j2 * 32;
        float4 av = a4[i], wv = w4[i];
        acc += tanh_fast(pv[j2].x + av.x) * wv.x;
        acc += tanh_fast(pv[j2].y + av.y) * wv.y;
        acc += tanh_fast(pv[j2].z + av.z) * wv.z;
        acc += tanh_fast(pv[j2].w + av.w) * wv.w;
    }
#pragma unroll
    for (int o = 16; o > 0; o >>= 1) acc += __shfl_down_sync(FULL, acc, o);
    if (lane == 0) g_escore[idx] = __expf(acc + ba[0]);
}

// ---------------------------------------------------------------------------
// k_sum1: sum-only softmax stats (no max pass needed). grid (SC, BATCH);
// each block sums 256 escores -> g_ps. Tiny, wide, latency-tolerant.
// ---------------------------------------------------------------------------
__global__ void k_sum1() {
    int ch = blockIdx.x, b = blockIdx.y, t = threadIdx.x;
    int w = t >> 5, lane = t & 31;
    __shared__ float red[8];

    float e = g_escore[b * L + ch * SLEN + t];
#pragma unroll
    for (int o = 16; o > 0; o >>= 1) e += __shfl_xor_sync(FULL, e, o);
    if (lane == 0) red[w] = e;
    __syncthreads();
    if (t == 0) {
        float v = 0.f;
#pragma unroll
        for (int i = 0; i < 8; i++) v += red[i];
        g_ps[b * SC + ch] = v;
    }
}

// ---------------------------------------------------------------------------
// k_wsum: per-(chunk, b) weighted-sum partials. Trivial prologue: thread 0
// sums the 8 per-b partial sums (L2 loads) -> inv. Ballot-compacts nonzero
// weights (masked escores are exactly 0 -> skipping is bit-exact), streams
// the surviving rows, and fuses the final cross-chunk reduce via a per-b
// counter with fence -> barrier -> atomic release ordering.
// ---------------------------------------------------------------------------
__global__ void k_wsum(const float* __restrict__ af, float* __restrict__ out) {
    int c = blockIdx.x, b = blockIdx.y, t = threadIdx.x;
    __shared__ float swraw[LC];
    __shared__ float swv[LC];
    __shared__ int   sidx[LC];
    __shared__ int   scount;
    __shared__ float s_inv;
    __shared__ int   s_ticket;

    if (t == 0) {
        float sum = 0.f;
#pragma unroll
        for (int i = 0; i < SC; i++) sum += g_ps[b * SC + i];
        s_inv = 1.0f / sum;
    }
    int lbase = b * L + c * LC;
    if (t < LC) swraw[t] = g_escore[lbase + t];
    __syncthreads();

    // Ballot-compact nonzero weights (weight = escore * inv).
    if (t < 32) {
        int base = 0;
        float inv = s_inv;
#pragma unroll
        for (int k = 0; k < LC; k += 32) {
            float e = swraw[k + t];
            unsigned m = __ballot_sync(FULL, e != 0.f);
            if (e != 0.f) {
                int pos = base + __popc(m & ((1u << t) - 1u));
                swv[pos]  = e * inv;
                sidx[pos] = k + t;
            }
            base += __popc(m);
        }
        if (t == 0) scount = base;
    }
    __syncthreads();

    const float4* a4 = (const float4*)(af + (size_t)lbase * R);
    float4 acc = make_float4(0.f, 0.f, 0.f, 0.f);
    int n = scount;
    int j = 0;
    for (; j + 4 <= n; j += 4) {
        float w0 = swv[j],     w1 = swv[j + 1];
        float w2 = swv[j + 2], w3 = swv[j + 3];
        float4 v0 = ldcs4(a4 + (size_t)sidx[j]     * (R / 4) + t);
        float4 v1 = ldcs4(a4 + (size_t)sidx[j + 1] * (R / 4) + t);
        float4 v2 = ldcs4(a4 + (size_t)sidx[j + 2] * (R / 4) + t);
        float4 v3 = ldcs4(a4 + (size_t)sidx[j + 3] * (R / 4) + t);
        acc.x += w0 * v0.x; acc.y += w0 * v0.y; acc.z += w0 * v0.z; acc.w += w0 * v0.w;
        acc.x += w1 * v1.x; acc.y += w1 * v1.y; acc.z += w1 * v1.z; acc.w += w1 * v1.w;
        acc.x += w2 * v2.x; acc.y += w2 * v2.y; acc.z += w2 * v2.z; acc.w += w2 * v2.w;
        acc.x += w3 * v3.x; acc.y += w3 * v3.y; acc.z += w3 * v3.z; acc.w += w3 * v3.w;
    }
    for (; j < n; j++) {
        float w  = swv[j];
        float4 v = ldcs4(a4 + (size_t)sidx[j] * (R / 4) + t);
        acc.x += w * v.x; acc.y += w * v.y; acc.z += w * v.z; acc.w += w * v.w;
    }
    ((float4*)(g_part + ((size_t)c * BATCH + b) * R))[t] = acc;

    // Fused final reduce with correct release ordering.
    __threadfence();     // each thread: my partial store ordered
    __syncthreads();     // all threads fenced => whole block's partial visible
    if (t == 0) s_ticket = atomicAdd(&g_cnt[b], 1);
    __syncthreads();
    if (s_ticket == CH - 1) {
        float4 s = make_float4(0.f, 0.f, 0.f, 0.f);
#pragma unroll
        for (int cc = 0; cc < CH; cc++) {
            float4 v = ldcg4((const float4*)(g_part + ((size_t)cc * BATCH + b) * R) + t);
            s.x += v.x; s.y += v.y; s.z += v.z; s.w += v.w;
        }
        ((float4*)(out + (size_t)b * R))[t] = s;
        if (t == 0) g_cnt[b] = 0;   // self-reset for next launch/replay
    }
}

// ---------------------------------------------------------------------------
extern "C" void kernel_launch(void* const* d_in, const int* in_sizes, int n_in,
                              void* d_out, int out_size) {
    const float* h    = (const float*)d_in[0];
    const float* af   = (const float*)d_in[1];
    const float* p    = (const float*)d_in[2];
    const void*  mask = d_in[3];
    const float* Wh   = (const float*)d_in[4];
    const float* bh   = (const float*)d_in[5];
    const float* Wa   = (const float*)d_in[6];
    const float* ba   = (const float*)d_in[7];
    float* out = (float*)d_out;

    k_att_h<<<257, 256>>>(h, Wh, bh, (const unsigned int*)mask);
    k_compact<<<BATCH, 256>>>((const unsigned char*)mask, (const int*)mask);
    k_scores<<<8192, 256>>>(p, Wa, ba);
    k_sum1<<<dim3(SC, BATCH), 256>>>();
    k_wsum<<<dim3(CH, BATCH), 256>>>(af, out);
}